// round 15
// baseline (speedup 1.0000x reference)
#include <cuda_runtime.h>
#include <cstdint>

// Problem shape (fixed by the dataset)
#define T_MAX 16384
#define HID   512
#define GATES 2048   // 4*HID
#define NCTA  64     // persistent CTAs (cooperative launch)
#define NTHR  256

// ---------------------------------------------------------------------------
// Device scratch (no cudaMalloc allowed)
// ---------------------------------------------------------------------------
// Tagged h exchange: element = (tag<<32) | bits(f32 value). tag = step+1.
// Double-buffered by step parity. gates_kernel zeroes tags each replay.
__device__ unsigned long long g_htag[2][HID];
__device__ float g_xg[(size_t)T_MAX * GATES];   // precomputed input gates

// ---------------------------------------------------------------------------
// Helpers
// ---------------------------------------------------------------------------
__device__ __forceinline__ void fma2(unsigned long long& a,
                                     unsigned long long w,
                                     unsigned long long h) {
    asm("fma.rn.f32x2 %0, %1, %2, %0;" : "+l"(a) : "l"(w), "l"(h));
}
// STRONG relaxed gpu-scope 16B poll load: always L2-coherent, never stale L1.
__device__ __forceinline__ void ld_strong2(const void* p,
                                           unsigned long long& a,
                                           unsigned long long& b) {
    asm volatile("ld.relaxed.gpu.global.v2.u64 {%0,%1},[%2];"
                 : "=l"(a), "=l"(b) : "l"(p) : "memory");
}
// STRONG relaxed gpu-scope 8B publish store.
__device__ __forceinline__ void st_strong(unsigned long long* p,
                                          unsigned long long v) {
    asm volatile("st.relaxed.gpu.global.u64 [%0],%1;"
                 :: "l"(p), "l"(v) : "memory");
}
__device__ __forceinline__ void unpack2(unsigned long long a, float& lo, float& hi) {
    asm("mov.b64 {%0,%1},%2;" : "=f"(lo), "=f"(hi) : "l"(a));
}
__device__ __forceinline__ unsigned long long pack2u(unsigned lo, unsigned hi) {
    unsigned long long v;
    asm("mov.b64 %0,{%1,%2};" : "=l"(v) : "r"(lo), "r"(hi));
    return v;
}
__device__ __forceinline__ unsigned hi32(unsigned long long v) {
    unsigned lo, hi;
    asm("mov.b64 {%0,%1},%2;" : "=r"(lo), "=r"(hi) : "l"(v));
    return hi;
}
__device__ __forceinline__ unsigned lo32(unsigned long long v) {
    unsigned lo, hi;
    asm("mov.b64 {%0,%1},%2;" : "=r"(lo), "=r"(hi) : "l"(v));
    return lo;
}
__device__ __forceinline__ float tanh_mufu(float x) {      // HW MUFU.TANH
    float t; asm("tanh.approx.f32 %0,%1;" : "=f"(t) : "f"(x)); return t;
}

// ---------------------------------------------------------------------------
// Kernel A: x_gates precompute + tag reset (runs before lstm each replay).
// ---------------------------------------------------------------------------
__global__ void __launch_bounds__(256) gates_kernel(
    const float* __restrict__ x,    // [T,1,32]
    const float* __restrict__ Wih,  // [2048,32]
    const float* __restrict__ bih,  // [2048]
    const float* __restrict__ bhh)  // [2048]
{
    if (blockIdx.x == 0) {
        for (int i = threadIdx.x; i < 2 * HID; i += 256)
            st_strong(&((unsigned long long*)g_htag)[i], 0ull);
    }

    __shared__ __align__(16) float xs[64 * 32];
    const int t0 = blockIdx.x * 64;
    for (int i = threadIdx.x; i < 64 * 32; i += 256)
        xs[i] = x[(size_t)t0 * 32 + i];
    __syncthreads();

    for (int r = threadIdx.x; r < GATES; r += 256) {
        float4 w[8];
#pragma unroll
        for (int i = 0; i < 8; i++)
            w[i] = __ldg((const float4*)(Wih + (size_t)r * 32 + 4 * i));
        const float b = __ldg(bih + r) + __ldg(bhh + r);
#pragma unroll 4
        for (int tt = 0; tt < 64; ++tt) {
            float acc = b;
#pragma unroll
            for (int i = 0; i < 8; i++) {
                float4 xv = *(const float4*)&xs[tt * 32 + 4 * i];
                acc = fmaf(w[i].x, xv.x, acc);
                acc = fmaf(w[i].y, xv.y, acc);
                acc = fmaf(w[i].z, xv.z, acc);
                acc = fmaf(w[i].w, xv.w, acc);
            }
            g_xg[(size_t)(t0 + tt) * GATES + r] = acc;
        }
    }
}

// ---------------------------------------------------------------------------
// Kernel B: persistent sequential LSTM, 64 CTAs x 256, cooperative.
// R14 skeleton VERBATIM (best known: 13659us). R15 = detect-path trims:
//  (1) speculative staging: STS inside the poll loop, so the staging store
//      doesn't wait on the final round's predicate+branch resolution
//      (warp-local smem traffic only — poll L2 traffic unchanged);
//  (2) fused tag check: (hi0^tag)|(hi1^tag) -> LOP3+ISETP (shorter poll
//      period, earlier branch resolve).
// ---------------------------------------------------------------------------
__global__ void __launch_bounds__(NTHR, 1) lstm_kernel(
    const float* __restrict__ Whh,   // [2048,512]
    const float* __restrict__ Wlin,  // [1,512]
    const float* __restrict__ blin,  // [1]
    float* __restrict__ out,         // [1]
    int T)
{
    const int tid = threadIdx.x;
    const int c   = blockIdx.x;
    const int r   = tid & 31;
    const int seg = tid >> 5;
    const int q   = r >> 3;
    const int uu  = r & 7;
    const int grow = q * HID + c * 8 + uu;   // gate row (warp0 reduce role)

    // loop-invariant activation selects (warp0 lanes):
    const float act_pre = (q == 2) ? 1.f : 0.5f;
    const float act_mul = (q == 2) ? 1.f : 0.5f;
    const float act_off = (q == 2) ? 0.f : 0.5f;

    // Weight slice -> registers (32 packed f32x2 = 64 floats)
    unsigned long long w[32];
    {
        const ulonglong2* wp =
            (const ulonglong2*)(Whh + (size_t)grow * HID + seg * 64);
#pragma unroll
        for (int i = 0; i < 16; i++) {
            ulonglong2 v = __ldg(&wp[i]);
            w[2 * i] = v.x; w[2 * i + 1] = v.y;
        }
    }

    __shared__ __align__(16) float hs[HID];
    // Transposed partials (R12): pitch 12 floats; warp0 reduce = 2x LDS.128.
    __shared__ __align__(16) float partT[32][12];
    float c_state = 0.f;

    // Per-parity pointers (hoisted off the per-step critical path)
    const unsigned long long* psrc[2] = {
        &g_htag[0][seg * 64 + 2 * r], &g_htag[1][seg * 64 + 2 * r] };
    unsigned long long* pdst[2] = {
        &g_htag[0][c * 8 + uu], &g_htag[1][c * 8 + uu] };
    float2* stage = &((float2*)hs)[seg * 32 + r];

    // Publish h_0 = 0 with tag 1 (gates_kernel's reset is stream-ordered first)
    if (tid < 8)
        st_strong(&g_htag[0][c * 8 + tid], 1ull << 32);

    // xg prefetch pipeline (warp0 only consumes xg)
    float xg_next = 0.f;
    if (seg == 0) xg_next = __ldg(&g_xg[grow]);   // t = 0

    unsigned tag_poll = 1u;   // tag expected this step   (t+1)
    unsigned tag_pub  = 2u;   // tag published this step  (t+2)

    for (int t = 0; t < T; ++t) {
        const float xgv = xg_next;

        // ---- 1-deep per-lane poll, FIRST thing after barrier release.
        //      Speculative staging: store every round; on exit smem already
        //      holds the passing values (store no longer waits on the final
        //      predicate+branch). Fused XOR tag check. ----
        {
            const unsigned long long* src = psrc[t & 1];
            unsigned long long p0, p1;
            unsigned bad;
            do {
                ld_strong2(src, p0, p1);
                *stage = make_float2(__uint_as_float(lo32(p0)),
                                     __uint_as_float(lo32(p1)));
                bad = (hi32(p0) ^ tag_poll) | (hi32(p1) ^ tag_poll);
            } while (bad != 0u);
        }
        // xg prefetch for t+1: issued after staging, off the poll-issue slot
        if (seg == 0) {
            int tn = (t + 1 < T) ? (t + 1) : t;
            xg_next = __ldg(&g_xg[(size_t)tn * GATES + grow]);
        }
        __syncwarp();

        // matvec: 32 packed FMAs per thread, weights in regs, h via LDS bcast
        unsigned long long a0 = 0ull, a1 = 0ull, a2 = 0ull, a3 = 0ull;
        const unsigned long long* hseg = (const unsigned long long*)&hs[seg * 64];
#pragma unroll
        for (int i = 0; i < 32; i += 4) {
            fma2(a0, w[i + 0], hseg[i + 0]);
            fma2(a1, w[i + 1], hseg[i + 1]);
            fma2(a2, w[i + 2], hseg[i + 2]);
            fma2(a3, w[i + 3], hseg[i + 3]);
        }
        float x0, x1, x2, x3, x4, x5, x6, x7;
        unpack2(a0, x0, x1); unpack2(a1, x2, x3);
        unpack2(a2, x4, x5); unpack2(a3, x6, x7);
        partT[r][seg] = ((x0 + x1) + (x2 + x3)) + ((x4 + x5) + (x6 + x7));
        __syncthreads();   // bar #1: partT RAW for warp0

        if (seg == 0) {
            // reduce: 2x LDS.128 over this row's 8 segment partials
            float4 A = *(const float4*)&partT[r][0];
            float4 B = *(const float4*)&partT[r][4];
            float s = xgv + (((A.x + A.y) + (A.z + A.w)) +
                             ((B.x + B.y) + (B.z + B.w)));
            // single-MUFU activation, branch-free
            float a = fmaf(act_mul, tanh_mufu(act_pre * s), act_off);
            float fv = __shfl_sync(0xffffffffu, a, r + 8);
            float gv = __shfl_sync(0xffffffffu, a, r + 16);
            float ov = __shfl_sync(0xffffffffu, a, r + 24);
            if (r < 8) {
                c_state = fmaf(fv, c_state, a * gv);
                float hval = ov * tanh_mufu(c_state);
                st_strong(pdst[(t + 1) & 1],
                          pack2u(__float_as_uint(hval), tag_pub));
            }
        }
        tag_poll += 1;
        tag_pub  += 1;
        // bar #2: parks warps 1-7 during warp0's tail -> poll-quiet publish
        // window (empirically load-bearing); covers partT/hs WAR hazards.
        __syncthreads();
    }

    // Final projection (CTA 0, warp 0): poll h_T (all segments), dot W_lin
    if (c == 0 && seg == 0) {
        const unsigned tag32 = (unsigned)(T + 1);
        const unsigned long long* src = &g_htag[T & 1][0];
        unsigned long long p[16];
        for (;;) {
            bool ok = true;
#pragma unroll
            for (int k = 0; k < 8; k++) {
                ld_strong2(src + 2 * r + 64 * k, p[2 * k], p[2 * k + 1]);
                ok &= (hi32(p[2 * k]) == tag32) &
                      (hi32(p[2 * k + 1]) == tag32);
            }
            if (__all_sync(0xffffffffu, ok)) break;
        }
        float s = 0.f;
#pragma unroll
        for (int k = 0; k < 8; k++) {
            int e = 2 * r + 64 * k;
            float2 wl = __ldg((const float2*)(Wlin + e));
            s = fmaf(__uint_as_float(lo32(p[2 * k])),     wl.x, s);
            s = fmaf(__uint_as_float(lo32(p[2 * k + 1])), wl.y, s);
        }
#pragma unroll
        for (int o = 16; o; o >>= 1) s += __shfl_xor_sync(0xffffffffu, s, o);
        if (r == 0) out[0] = s + __ldg(blin);
    }
}

// ---------------------------------------------------------------------------
// Launch
// ---------------------------------------------------------------------------
extern "C" void kernel_launch(void* const* d_in, const int* in_sizes, int n_in,
                              void* d_out, int out_size)
{
    const float* x    = (const float*)d_in[0];
    const float* Wih  = (const float*)d_in[1];
    const float* Whh  = (const float*)d_in[2];
    const float* bih  = (const float*)d_in[3];
    const float* bhh  = (const float*)d_in[4];
    const float* Wlin = (const float*)d_in[5];
    const float* blin = (const float*)d_in[6];

    int T = in_sizes[0] / 32;
    if (T > T_MAX) T = T_MAX;

    gates_kernel<<<T / 64, 256>>>(x, Wih, bih, bhh);

    cudaLaunchConfig_t cfg = {};
    cfg.gridDim  = dim3(NCTA, 1, 1);
    cfg.blockDim = dim3(NTHR, 1, 1);
    cfg.dynamicSmemBytes = 0;
    cudaLaunchAttribute attr[1];
    attr[0].id = cudaLaunchAttributeCooperative;
    attr[0].val.cooperative = 1;
    cfg.attrs = attr;
    cfg.numAttrs = 1;
    cudaLaunchKernelEx(&cfg, lstm_kernel,
                       Whh, Wlin, blin, (float*)d_out, T);
}

// round 16
// speedup vs baseline: 1.0056x; 1.0056x over previous
#include <cuda_runtime.h>
#include <cstdint>

// Problem shape (fixed by the dataset)
#define T_MAX 16384
#define HID   512
#define GATES 2048   // 4*HID
#define NCTA  64     // persistent CTAs (cooperative launch)
#define NTHR  256

// ---------------------------------------------------------------------------
// Device scratch (no cudaMalloc allowed)
// ---------------------------------------------------------------------------
// Tagged h exchange: element = (tag<<32) | bits(f32 value). tag = step+1.
// Double-buffered by step parity. gates_kernel zeroes tags each replay.
__device__ unsigned long long g_htag[2][HID];
__device__ float g_xg[(size_t)T_MAX * GATES];   // precomputed input gates

// ---------------------------------------------------------------------------
// Helpers
// ---------------------------------------------------------------------------
__device__ __forceinline__ void fma2(unsigned long long& a,
                                     unsigned long long w,
                                     unsigned long long h) {
    asm("fma.rn.f32x2 %0, %1, %2, %0;" : "+l"(a) : "l"(w), "l"(h));
}
// STRONG relaxed gpu-scope 16B poll load: always L2-coherent, never stale L1.
__device__ __forceinline__ void ld_strong2(const void* p,
                                           unsigned long long& a,
                                           unsigned long long& b) {
    asm volatile("ld.relaxed.gpu.global.v2.u64 {%0,%1},[%2];"
                 : "=l"(a), "=l"(b) : "l"(p) : "memory");
}
// STRONG relaxed gpu-scope 8B publish store.
__device__ __forceinline__ void st_strong(unsigned long long* p,
                                          unsigned long long v) {
    asm volatile("st.relaxed.gpu.global.u64 [%0],%1;"
                 :: "l"(p), "l"(v) : "memory");
}
__device__ __forceinline__ void unpack2(unsigned long long a, float& lo, float& hi) {
    asm("mov.b64 {%0,%1},%2;" : "=f"(lo), "=f"(hi) : "l"(a));
}
__device__ __forceinline__ unsigned long long pack2u(unsigned lo, unsigned hi) {
    unsigned long long v;
    asm("mov.b64 %0,{%1,%2};" : "=l"(v) : "r"(lo), "r"(hi));
    return v;
}
__device__ __forceinline__ unsigned hi32(unsigned long long v) {
    unsigned lo, hi;
    asm("mov.b64 {%0,%1},%2;" : "=r"(lo), "=r"(hi) : "l"(v));
    return hi;
}
__device__ __forceinline__ unsigned lo32(unsigned long long v) {
    unsigned lo, hi;
    asm("mov.b64 {%0,%1},%2;" : "=r"(lo), "=r"(hi) : "l"(v));
    return lo;
}
__device__ __forceinline__ float tanh_mufu(float x) {      // HW MUFU.TANH
    float t; asm("tanh.approx.f32 %0,%1;" : "=f"(t) : "f"(x)); return t;
}

// ---------------------------------------------------------------------------
// Kernel A: x_gates precompute + tag reset (runs before lstm each replay).
// ---------------------------------------------------------------------------
__global__ void __launch_bounds__(256) gates_kernel(
    const float* __restrict__ x,    // [T,1,32]
    const float* __restrict__ Wih,  // [2048,32]
    const float* __restrict__ bih,  // [2048]
    const float* __restrict__ bhh)  // [2048]
{
    if (blockIdx.x == 0) {
        for (int i = threadIdx.x; i < 2 * HID; i += 256)
            st_strong(&((unsigned long long*)g_htag)[i], 0ull);
    }

    __shared__ __align__(16) float xs[64 * 32];
    const int t0 = blockIdx.x * 64;
    for (int i = threadIdx.x; i < 64 * 32; i += 256)
        xs[i] = x[(size_t)t0 * 32 + i];
    __syncthreads();

    for (int r = threadIdx.x; r < GATES; r += 256) {
        float4 w[8];
#pragma unroll
        for (int i = 0; i < 8; i++)
            w[i] = __ldg((const float4*)(Wih + (size_t)r * 32 + 4 * i));
        const float b = __ldg(bih + r) + __ldg(bhh + r);
#pragma unroll 4
        for (int tt = 0; tt < 64; ++tt) {
            float acc = b;
#pragma unroll
            for (int i = 0; i < 8; i++) {
                float4 xv = *(const float4*)&xs[tt * 32 + 4 * i];
                acc = fmaf(w[i].x, xv.x, acc);
                acc = fmaf(w[i].y, xv.y, acc);
                acc = fmaf(w[i].z, xv.z, acc);
                acc = fmaf(w[i].w, xv.w, acc);
            }
            g_xg[(size_t)(t0 + tt) * GATES + r] = acc;
        }
    }
}

// ---------------------------------------------------------------------------
// Kernel B: persistent sequential LSTM, 64 CTAs x 256, cooperative.
// R14 skeleton EXACT (best measured: 13659us):
//  - 1-deep per-lane strong poll, first instruction after barrier release
//  - per-parity poll-src / publish-dst pointers (select, no IMAD on path)
//  - post-loop staging to warp-private smem
//  - xg prefetch issued after staging (off the poll-issue slot)
//  - packed-f32x2 matvec from registers, LDS broadcast h
//  - transposed partials partT[32][12], warp0 reduce = 2x LDS.128
//  - single-MUFU activations; register-held publish tag
//  - TWO __syncthreads per step (trailing = poll-quiet publish window)
// R16 delta: XOR-fused tag check only (one fewer op per poll round).
// ---------------------------------------------------------------------------
__global__ void __launch_bounds__(NTHR, 1) lstm_kernel(
    const float* __restrict__ Whh,   // [2048,512]
    const float* __restrict__ Wlin,  // [1,512]
    const float* __restrict__ blin,  // [1]
    float* __restrict__ out,         // [1]
    int T)
{
    const int tid = threadIdx.x;
    const int c   = blockIdx.x;
    const int r   = tid & 31;
    const int seg = tid >> 5;
    const int q   = r >> 3;
    const int uu  = r & 7;
    const int grow = q * HID + c * 8 + uu;   // gate row (warp0 reduce role)

    // loop-invariant activation selects (warp0 lanes):
    const float act_pre = (q == 2) ? 1.f : 0.5f;
    const float act_mul = (q == 2) ? 1.f : 0.5f;
    const float act_off = (q == 2) ? 0.f : 0.5f;

    // Weight slice -> registers (32 packed f32x2 = 64 floats)
    unsigned long long w[32];
    {
        const ulonglong2* wp =
            (const ulonglong2*)(Whh + (size_t)grow * HID + seg * 64);
#pragma unroll
        for (int i = 0; i < 16; i++) {
            ulonglong2 v = __ldg(&wp[i]);
            w[2 * i] = v.x; w[2 * i + 1] = v.y;
        }
    }

    __shared__ __align__(16) float hs[HID];
    // Transposed partials (R12): pitch 12 floats; warp0 reduce = 2x LDS.128.
    __shared__ __align__(16) float partT[32][12];
    float c_state = 0.f;

    // Per-parity pointers (hoisted off the per-step critical path)
    const unsigned long long* psrc[2] = {
        &g_htag[0][seg * 64 + 2 * r], &g_htag[1][seg * 64 + 2 * r] };
    unsigned long long* pdst[2] = {
        &g_htag[0][c * 8 + uu], &g_htag[1][c * 8 + uu] };

    // Publish h_0 = 0 with tag 1 (gates_kernel's reset is stream-ordered first)
    if (tid < 8)
        st_strong(&g_htag[0][c * 8 + tid], 1ull << 32);

    // xg prefetch pipeline (warp0 only consumes xg)
    float xg_next = 0.f;
    if (seg == 0) xg_next = __ldg(&g_xg[grow]);   // t = 0

    unsigned tag_poll = 1u;   // tag expected this step   (t+1)
    unsigned tag_pub  = 2u;   // tag published this step  (t+2)

    for (int t = 0; t < T; ++t) {
        const float xgv = xg_next;

        // ---- 1-deep per-lane poll, FIRST thing after barrier release.
        //      XOR-fused tag check (LOP3 + ISETP per round). ----
        {
            const unsigned long long* src = psrc[t & 1];
            unsigned long long p0, p1;
            unsigned bad;
            do {
                ld_strong2(src, p0, p1);
                bad = (hi32(p0) ^ tag_poll) | (hi32(p1) ^ tag_poll);
            } while (bad != 0u);
            ((float2*)hs)[seg * 32 + r] = make_float2(
                __uint_as_float(lo32(p0)), __uint_as_float(lo32(p1)));
        }
        // xg prefetch for t+1: issued after staging, off the poll-issue slot
        if (seg == 0) {
            int tn = (t + 1 < T) ? (t + 1) : t;
            xg_next = __ldg(&g_xg[(size_t)tn * GATES + grow]);
        }
        __syncwarp();

        // matvec: 32 packed FMAs per thread, weights in regs, h via LDS bcast
        unsigned long long a0 = 0ull, a1 = 0ull, a2 = 0ull, a3 = 0ull;
        const unsigned long long* hseg = (const unsigned long long*)&hs[seg * 64];
#pragma unroll
        for (int i = 0; i < 32; i += 4) {
            fma2(a0, w[i + 0], hseg[i + 0]);
            fma2(a1, w[i + 1], hseg[i + 1]);
            fma2(a2, w[i + 2], hseg[i + 2]);
            fma2(a3, w[i + 3], hseg[i + 3]);
        }
        float x0, x1, x2, x3, x4, x5, x6, x7;
        unpack2(a0, x0, x1); unpack2(a1, x2, x3);
        unpack2(a2, x4, x5); unpack2(a3, x6, x7);
        partT[r][seg] = ((x0 + x1) + (x2 + x3)) + ((x4 + x5) + (x6 + x7));
        __syncthreads();   // bar #1: partT RAW for warp0

        if (seg == 0) {
            // reduce: 2x LDS.128 over this row's 8 segment partials
            float4 A = *(const float4*)&partT[r][0];
            float4 B = *(const float4*)&partT[r][4];
            float s = xgv + (((A.x + A.y) + (A.z + A.w)) +
                             ((B.x + B.y) + (B.z + B.w)));
            // single-MUFU activation, branch-free
            float a = fmaf(act_mul, tanh_mufu(act_pre * s), act_off);
            float fv = __shfl_sync(0xffffffffu, a, r + 8);
            float gv = __shfl_sync(0xffffffffu, a, r + 16);
            float ov = __shfl_sync(0xffffffffu, a, r + 24);
            if (r < 8) {
                c_state = fmaf(fv, c_state, a * gv);
                float hval = ov * tanh_mufu(c_state);
                st_strong(pdst[(t + 1) & 1],
                          pack2u(__float_as_uint(hval), tag_pub));
            }
        }
        tag_poll += 1;
        tag_pub  += 1;
        // bar #2: parks warps 1-7 during warp0's tail -> poll-quiet publish
        // window (empirically load-bearing); covers partT/hs WAR hazards.
        __syncthreads();
    }

    // Final projection (CTA 0, warp 0): poll h_T (all segments), dot W_lin
    if (c == 0 && seg == 0) {
        const unsigned tag32 = (unsigned)(T + 1);
        const unsigned long long* src = &g_htag[T & 1][0];
        unsigned long long p[16];
        for (;;) {
            bool ok = true;
#pragma unroll
            for (int k = 0; k < 8; k++) {
                ld_strong2(src + 2 * r + 64 * k, p[2 * k], p[2 * k + 1]);
                ok &= (hi32(p[2 * k]) == tag32) &
                      (hi32(p[2 * k + 1]) == tag32);
            }
            if (__all_sync(0xffffffffu, ok)) break;
        }
        float s = 0.f;
#pragma unroll
        for (int k = 0; k < 8; k++) {
            int e = 2 * r + 64 * k;
            float2 wl = __ldg((const float2*)(Wlin + e));
            s = fmaf(__uint_as_float(lo32(p[2 * k])),     wl.x, s);
            s = fmaf(__uint_as_float(lo32(p[2 * k + 1])), wl.y, s);
        }
#pragma unroll
        for (int o = 16; o; o >>= 1) s += __shfl_xor_sync(0xffffffffu, s, o);
        if (r == 0) out[0] = s + __ldg(blin);
    }
}

// ---------------------------------------------------------------------------
// Launch
// ---------------------------------------------------------------------------
extern "C" void kernel_launch(void* const* d_in, const int* in_sizes, int n_in,
                              void* d_out, int out_size)
{
    const float* x    = (const float*)d_in[0];
    const float* Wih  = (const float*)d_in[1];
    const float* Whh  = (const float*)d_in[2];
    const float* bih  = (const float*)d_in[3];
    const float* bhh  = (const float*)d_in[4];
    const float* Wlin = (const float*)d_in[5];
    const float* blin = (const float*)d_in[6];

    int T = in_sizes[0] / 32;
    if (T > T_MAX) T = T_MAX;

    gates_kernel<<<T / 64, 256>>>(x, Wih, bih, bhh);

    cudaLaunchConfig_t cfg = {};
    cfg.gridDim  = dim3(NCTA, 1, 1);
    cfg.blockDim = dim3(NTHR, 1, 1);
    cfg.dynamicSmemBytes = 0;
    cudaLaunchAttribute attr[1];
    attr[0].id = cudaLaunchAttributeCooperative;
    attr[0].val.cooperative = 1;
    cfg.attrs = attr;
    cfg.numAttrs = 1;
    cudaLaunchKernelEx(&cfg, lstm_kernel,
                       Whh, Wlin, blin, (float*)d_out, T);
}